// round 12
// baseline (speedup 1.0000x reference)
#include <cuda_runtime.h>
#include <cstdint>

// SoftReordering, R11: R8 structure + occupancy 2 -> 3 CTAs/SM.
//   NBUF 3 -> 2 (smem 86KB -> 58KB), launch_bounds(256,3) (regs ~84),
//   per-c x loads to shrink the live set. Pipeline per phase:
//   cp_wait<0>(my slab p) -> barrier -> stage(p+1 into buffer of p-1)
//   -> compute p (cp.async of p+1 overlaps compute of p).

#define SSEQ 1024
#define EE   1024
#define WW   7
#define WE   7168
#define HALF 512                     // floats per phase (e-half)
#define SLABF (14 * HALF)            // 28KB slab: 14 (t,v) rows x 512
#define NBUF 2
#define PART_OFF (NBUF * SLABF)
#define PART_FLOATS (2 * 4 * 2 * 7 * 2 * 2)   // ec,bg,tt,v,pair,half = 448
#define SMEM_BYTES ((NBUF * SLABF + PART_FLOATS) * 4)   // 59136

__device__ __forceinline__ uint32_t smem_u32(const void* p) {
    uint32_t a;
    asm("{ .reg .u64 t; cvta.to.shared.u64 t, %1; cvt.u32.u64 %0, t; }"
        : "=r"(a) : "l"(p));
    return a;
}
__device__ __forceinline__ void cp_async16(uint32_t saddr, const void* gptr) {
    asm volatile("cp.async.cg.shared.global [%0], [%1], 16;"
                 :: "r"(saddr), "l"(gptr));
}
__device__ __forceinline__ void cp_commit() {
    asm volatile("cp.async.commit_group;");
}
template <int N>
__device__ __forceinline__ void cp_wait() {
    asm volatile("cp.async.wait_group %0;" :: "n"(N));
}
__device__ __forceinline__ void ffma2(unsigned long long& d,
                                      unsigned long long a,
                                      unsigned long long b) {
    asm("fma.rn.f32x2 %0, %1, %2, %3;" : "=l"(d) : "l"(a), "l"(b), "l"(d));
}
__device__ __forceinline__ unsigned long long pack2(float lo, float hi) {
    unsigned long long p;
    asm("mov.b64 %0, {%1, %2};" : "=l"(p) : "f"(lo), "f"(hi));
    return p;
}
__device__ __forceinline__ unsigned long long pack_dup(float g) {
    unsigned long long p;
    asm("mov.b64 %0, {%1, %1};" : "=l"(p) : "f"(g));
    return p;
}
__device__ __forceinline__ float2 unpack2(unsigned long long v) {
    float2 r;
    asm("mov.b64 {%0, %1}, %2;" : "=f"(r.x), "=f"(r.y) : "l"(v));
    return r;
}
__device__ __forceinline__ unsigned long long add2(unsigned long long a,
                                                   unsigned long long b) {
    unsigned long long d;
    asm("add.rn.f32x2 %0, %1, %2;" : "=l"(d) : "l"(a), "l"(b));
    return d;
}
__device__ __forceinline__ unsigned long long shfl_xor_u64(unsigned long long v,
                                                           int m) {
    uint32_t lo = (uint32_t)v, hi = (uint32_t)(v >> 32);
    lo = __shfl_xor_sync(0xffffffffu, lo, m);
    hi = __shfl_xor_sync(0xffffffffu, hi, m);
    return ((unsigned long long)hi << 32) | lo;
}
__device__ __forceinline__ float tanh_ap(float x) {
    float r;
    asm("tanh.approx.f32 %0, %1;" : "=f"(r) : "f"(x));
    return r;
}

__global__ void __launch_bounds__(256, 3)
soft_reorder_kernel(const float* __restrict__ x,
                    const float* __restrict__ wgt,
                    const float* __restrict__ bias,
                    float* __restrict__ out) {
    extern __shared__ float smem[];
    unsigned long long* s_part =
        reinterpret_cast<unsigned long long*>(smem + PART_OFF);
    const float* s_partf = smem + PART_OFF;

    const int t0   = (int)blockIdx.x * 2;
    const int t1   = t0 + 1;
    const int tid  = threadIdx.x;
    const int lane = tid & 31;
    const int warp = tid >> 5;
    const int ec   = warp & 1;            // e-chunk (0: [0,256), 1: [256,512))
    const int b0   = (warp >> 1) << 2;    // batch group base (4 batches)
    const uint32_t sbase = smem_u32(smem);

    // Slab phase p = i*2+h: rows 0-6 = weight[t0, v, i*E + h*HALF ..],
    //                       rows 7-13 = weight[t1, v, (i-1)*E + h*HALF ..].
    auto stage = [&](int p, int buf) {
        const int i = p >> 1, h = p & 1;
        const int r = t0 - 3 + i;
        if (r >= 0 && r < SSEQ) {
            const uint32_t dst = sbase + (uint32_t)buf * (SLABF * 4);
#pragma unroll
            for (int k = 0; k < 7; ++k) {
                const int j   = tid + (k << 8);     // 0..1791
                const int row = j >> 7;             // 0..13
                const int col = (j & 127) << 2;
                const float* src;
                bool ok;
                if (row < 7) {
                    ok  = (i < 7);
                    src = wgt + (size_t)(t0 * WW + row) * WE
                              + (size_t)i * EE + h * HALF + col;
                } else {
                    ok  = (i >= 1);
                    src = wgt + (size_t)(t1 * WW + (row - 7)) * WE
                              + (size_t)(i - 1) * EE + h * HALF + col;
                }
                if (ok)
                    cp_async16(dst + (uint32_t)(row * HALF + col) * 4, src);
            }
        }
        cp_commit();
    };

    // ------------------------------------------------------------------
    // Step 1: acc[tt][v][pair] packed over batch pairs (b0+2p, b0+2p+1).
    // ------------------------------------------------------------------
    unsigned long long acc[2][7][2];
#pragma unroll
    for (int tt = 0; tt < 2; ++tt)
#pragma unroll
        for (int v = 0; v < 7; ++v)
#pragma unroll
            for (int pr = 0; pr < 2; ++pr)
                acc[tt][v][pr] = 0ull;

    stage(0, 0);
    for (int p = 0; p < 16; ++p) {
        cp_wait<0>();          // my slab-p group complete (only pending one)
        __syncthreads();       // slab p fully visible; all done with p-1
        if (p + 1 < 16) stage(p + 1, (p + 1) & 1);   // into buffer of p-1

        const int i = p >> 1, h = p & 1;
        const int r = t0 - 3 + i;
        if (r >= 0 && r < SSEQ) {
            const float* xr = x + ((size_t)b0 * SSEQ + r) * EE
                                + h * HALF + ec * 256 + (lane << 2);
            const float* wb = smem + (p & 1) * SLABF + ec * 256 + (lane << 2);
            const bool tap0 = (i < 7), tap1 = (i >= 1);
#pragma unroll
            for (int c = 0; c < 2; ++c) {
                const float* xc = xr + (c << 7);
                const float4 x0 = *reinterpret_cast<const float4*>(xc);
                const float4 x1 = *reinterpret_cast<const float4*>(
                    xc + (size_t)SSEQ * EE);
                const float4 x2 = *reinterpret_cast<const float4*>(
                    xc + (size_t)2 * SSEQ * EE);
                const float4 x3 = *reinterpret_cast<const float4*>(
                    xc + (size_t)3 * SSEQ * EE);
                unsigned long long pk[2][4];
                pk[0][0] = pack2(x0.x, x1.x);  pk[1][0] = pack2(x2.x, x3.x);
                pk[0][1] = pack2(x0.y, x1.y);  pk[1][1] = pack2(x2.y, x3.y);
                pk[0][2] = pack2(x0.z, x1.z);  pk[1][2] = pack2(x2.z, x3.z);
                pk[0][3] = pack2(x0.w, x1.w);  pk[1][3] = pack2(x2.w, x3.w);

                if (tap0) {
#pragma unroll
                    for (int v = 0; v < 7; ++v) {
                        const float4 wv = *reinterpret_cast<const float4*>(
                            wb + v * HALF + (c << 7));          // LDS.128
                        const float* wk = &wv.x;
#pragma unroll
                        for (int k = 0; k < 4; ++k) {
                            const unsigned long long dw = pack_dup(wk[k]);
                            ffma2(acc[0][v][0], dw, pk[0][k]);
                            ffma2(acc[0][v][1], dw, pk[1][k]);
                        }
                    }
                }
                if (tap1) {
#pragma unroll
                    for (int v = 0; v < 7; ++v) {
                        const float4 wv = *reinterpret_cast<const float4*>(
                            wb + (7 + v) * HALF + (c << 7));
                        const float* wk = &wv.x;
#pragma unroll
                        for (int k = 0; k < 4; ++k) {
                            const unsigned long long dw = pack_dup(wk[k]);
                            ffma2(acc[1][v][0], dw, pk[0][k]);
                            ffma2(acc[1][v][1], dw, pk[1][k]);
                        }
                    }
                }
            }
        }
    }

    // Lane reduction (packed halves stay separate: lo = batch 2p, hi = 2p+1),
    // then publish per-(ec,bg) partials to smem.
#pragma unroll
    for (int tt = 0; tt < 2; ++tt)
#pragma unroll
        for (int v = 0; v < 7; ++v)
#pragma unroll
            for (int pr = 0; pr < 2; ++pr) {
                unsigned long long s = acc[tt][v][pr];
#pragma unroll
                for (int o = 16; o > 0; o >>= 1)
                    s = add2(s, shfl_xor_u64(s, o));
                if (lane == 0)
                    s_part[(((ec << 2) | (warp >> 1)) * 14 + tt * 7 + v) * 2 + pr] = s;
            }
    __syncthreads();

    // ------------------------------------------------------------------
    // Step 2: warp owns batches (2*warp, 2*warp+1), both t's, 8 rows, full e.
    // ------------------------------------------------------------------
    const int sb0 = warp << 1;
    unsigned long long gg[2][7][2];       // [tt][tap][bb] gate, duplicated
#pragma unroll
    for (int bb = 0; bb < 2; ++bb) {
        const int sb  = sb0 + bb;
        const int bg2 = sb >> 2;
        const int pr  = (sb >> 1) & 1;
        const int hf  = sb & 1;
#pragma unroll
        for (int tt = 0; tt < 2; ++tt)
#pragma unroll
            for (int v = 0; v < 7; ++v) {
                const int base = ((bg2 * 14 + tt * 7 + v) * 2 + pr) * 2 + hf;
                const float z = s_partf[base]
                              + s_partf[(4 * 14 * 2) * 2 + base]   // ec=1 block
                              + bias[(t0 + tt) * WW + v];
                gg[tt][v][bb] = pack_dup(1.0f / (1.0f + __expf(-z)));
            }
    }

#pragma unroll
    for (int c = 0; c < 8; ++c) {
        const int e = (c << 7) + (lane << 2);
        const float* xe = x + (size_t)sb0 * SSEQ * EE + e;
        unsigned long long o[2][2][2];
#pragma unroll
        for (int tt = 0; tt < 2; ++tt)
#pragma unroll
            for (int bb = 0; bb < 2; ++bb) {
                o[tt][bb][0] = 0ull; o[tt][bb][1] = 0ull;
            }
#pragma unroll
        for (int i = 0; i < 8; ++i) {
            const int r = t0 - 3 + i;
            if (r >= 0 && r < SSEQ) {
                const ulonglong2 xA = *reinterpret_cast<const ulonglong2*>(
                    xe + (size_t)r * EE);
                const ulonglong2 xB = *reinterpret_cast<const ulonglong2*>(
                    xe + (size_t)(SSEQ + r) * EE);
                if (i < 7) {
                    ffma2(o[0][0][0], gg[0][i][0], xA.x);
                    ffma2(o[0][0][1], gg[0][i][0], xA.y);
                    ffma2(o[0][1][0], gg[0][i][1], xB.x);
                    ffma2(o[0][1][1], gg[0][i][1], xB.y);
                }
                if (i >= 1) {
                    ffma2(o[1][0][0], gg[1][i - 1][0], xA.x);
                    ffma2(o[1][0][1], gg[1][i - 1][0], xA.y);
                    ffma2(o[1][1][0], gg[1][i - 1][1], xB.x);
                    ffma2(o[1][1][1], gg[1][i - 1][1], xB.y);
                }
            }
        }
#pragma unroll
        for (int tt = 0; tt < 2; ++tt)
#pragma unroll
            for (int bb = 0; bb < 2; ++bb) {
                const float2 p0 = unpack2(o[tt][bb][0]);
                const float2 p1 = unpack2(o[tt][bb][1]);
                float4 ov;
                ov.x = tanh_ap(p0.x);
                ov.y = tanh_ap(p0.y);
                ov.z = tanh_ap(p1.x);
                ov.w = tanh_ap(p1.y);
                *reinterpret_cast<float4*>(
                    out + ((size_t)(sb0 + bb) * SSEQ + (tt ? t1 : t0)) * EE + e)
                    = ov;
            }
    }
}

extern "C" void kernel_launch(void* const* d_in, const int* in_sizes, int n_in,
                              void* d_out, int out_size) {
    const float* x    = (const float*)d_in[0];
    const float* wgt  = (const float*)d_in[1];
    const float* bias = (const float*)d_in[2];
    float* out        = (float*)d_out;

    static bool attr_set = false;
    if (!attr_set) {
        cudaFuncSetAttribute(soft_reorder_kernel,
                             cudaFuncAttributeMaxDynamicSharedMemorySize,
                             SMEM_BYTES);
        attr_set = true;
    }
    soft_reorder_kernel<<<SSEQ / 2, 256, SMEM_BYTES>>>(x, wgt, bias, out);
}

// round 13
// speedup vs baseline: 1.3492x; 1.3492x over previous
#include <cuda_runtime.h>
#include <cstdint>

// SoftReordering, R12: occ 3 with spill-proof registers.
//   8 warps = 8 batch-pairs; each warp: 2 batches (ONE f32x2 pair), both
//   taps, FULL 512-float e-half per phase (4 c-chunks). acc = 14 ull = 28
//   regs -> total live ~70 regs, fits launch_bounds(256,3) WITHOUT spills
//   (R11's failure). Weight LDS redundancy 8 (floor ~71us) traded for 24
//   warps/SM of latency cover. NBUF=2 (56KB smem, 3 CTAs = 169KB).

#define SSEQ 1024
#define EE   1024
#define WW   7
#define WE   7168
#define HALF 512                     // floats per phase (e-half)
#define SLABF (14 * HALF)            // 28KB slab: 14 (t,v) rows x 512
#define NBUF 2
#define PART_OFF (NBUF * SLABF)
#define PART_ULL (8 * 14)            // 8 warps x (2tt x 7v) packed pairs
#define SMEM_BYTES ((NBUF * SLABF) * 4 + PART_ULL * 8)   // 58240

__device__ __forceinline__ uint32_t smem_u32(const void* p) {
    uint32_t a;
    asm("{ .reg .u64 t; cvta.to.shared.u64 t, %1; cvt.u32.u64 %0, t; }"
        : "=r"(a) : "l"(p));
    return a;
}
__device__ __forceinline__ void cp_async16(uint32_t saddr, const void* gptr) {
    asm volatile("cp.async.cg.shared.global [%0], [%1], 16;"
                 :: "r"(saddr), "l"(gptr));
}
__device__ __forceinline__ void cp_commit() {
    asm volatile("cp.async.commit_group;");
}
template <int N>
__device__ __forceinline__ void cp_wait() {
    asm volatile("cp.async.wait_group %0;" :: "n"(N));
}
__device__ __forceinline__ void ffma2(unsigned long long& d,
                                      unsigned long long a,
                                      unsigned long long b) {
    asm("fma.rn.f32x2 %0, %1, %2, %3;" : "=l"(d) : "l"(a), "l"(b), "l"(d));
}
__device__ __forceinline__ unsigned long long pack2(float lo, float hi) {
    unsigned long long p;
    asm("mov.b64 %0, {%1, %2};" : "=l"(p) : "f"(lo), "f"(hi));
    return p;
}
__device__ __forceinline__ unsigned long long pack_dup(float g) {
    unsigned long long p;
    asm("mov.b64 %0, {%1, %1};" : "=l"(p) : "f"(g));
    return p;
}
__device__ __forceinline__ float2 unpack2(unsigned long long v) {
    float2 r;
    asm("mov.b64 {%0, %1}, %2;" : "=f"(r.x), "=f"(r.y) : "l"(v));
    return r;
}
__device__ __forceinline__ unsigned long long add2(unsigned long long a,
                                                   unsigned long long b) {
    unsigned long long d;
    asm("add.rn.f32x2 %0, %1, %2;" : "=l"(d) : "l"(a), "l"(b));
    return d;
}
__device__ __forceinline__ unsigned long long shfl_xor_u64(unsigned long long v,
                                                           int m) {
    uint32_t lo = (uint32_t)v, hi = (uint32_t)(v >> 32);
    lo = __shfl_xor_sync(0xffffffffu, lo, m);
    hi = __shfl_xor_sync(0xffffffffu, hi, m);
    return ((unsigned long long)hi << 32) | lo;
}
__device__ __forceinline__ float tanh_ap(float x) {
    float r;
    asm("tanh.approx.f32 %0, %1;" : "=f"(r) : "f"(x));
    return r;
}

__global__ void __launch_bounds__(256, 3)
soft_reorder_kernel(const float* __restrict__ x,
                    const float* __restrict__ wgt,
                    const float* __restrict__ bias,
                    float* __restrict__ out) {
    extern __shared__ float smem[];
    unsigned long long* s_part =
        reinterpret_cast<unsigned long long*>(smem + PART_OFF);
    const float* s_partf = smem + PART_OFF;

    const int t0   = (int)blockIdx.x * 2;
    const int t1   = t0 + 1;
    const int tid  = threadIdx.x;
    const int lane = tid & 31;
    const int warp = tid >> 5;
    const int b0   = warp << 1;           // warp's 2 batches (one f32x2 pair)
    const uint32_t sbase = smem_u32(smem);

    // Slab phase p = i*2+h: rows 0-6 = weight[t0, v, i*E + h*HALF ..],
    //                       rows 7-13 = weight[t1, v, (i-1)*E + h*HALF ..].
    auto stage = [&](int p, int buf) {
        const int i = p >> 1, h = p & 1;
        const int r = t0 - 3 + i;
        if (r >= 0 && r < SSEQ) {
            const uint32_t dst = sbase + (uint32_t)buf * (SLABF * 4);
#pragma unroll
            for (int k = 0; k < 7; ++k) {
                const int j   = tid + (k << 8);     // 0..1791
                const int row = j >> 7;             // 0..13
                const int col = (j & 127) << 2;
                const float* src;
                bool ok;
                if (row < 7) {
                    ok  = (i < 7);
                    src = wgt + (size_t)(t0 * WW + row) * WE
                              + (size_t)i * EE + h * HALF + col;
                } else {
                    ok  = (i >= 1);
                    src = wgt + (size_t)(t1 * WW + (row - 7)) * WE
                              + (size_t)(i - 1) * EE + h * HALF + col;
                }
                if (ok)
                    cp_async16(dst + (uint32_t)(row * HALF + col) * 4, src);
            }
        }
        cp_commit();
    };

    // ------------------------------------------------------------------
    // Step 1: acc[tt][v], ONE batch pair per warp, full 512-f half.
    // ------------------------------------------------------------------
    unsigned long long acc[2][7];
#pragma unroll
    for (int tt = 0; tt < 2; ++tt)
#pragma unroll
        for (int v = 0; v < 7; ++v)
            acc[tt][v] = 0ull;

    stage(0, 0);
    for (int p = 0; p < 16; ++p) {
        const int i = p >> 1, h = p & 1;
        const int r = t0 - 3 + i;
        const bool rv = (r >= 0 && r < SSEQ);

        // Front-batch first c-chunk's x (small live set: 8 floats).
        float4 xf0, xf1;
        const float* xr = x + ((size_t)b0 * SSEQ + r) * EE
                            + h * HALF + (lane << 2);
        if (rv) {
            xf0 = *reinterpret_cast<const float4*>(xr);
            xf1 = *reinterpret_cast<const float4*>(xr + (size_t)SSEQ * EE);
        }

        cp_wait<0>();          // slab p complete (sole pending group)
        __syncthreads();       // visible to all; all warps done with p-1
        if (p + 1 < 16) stage(p + 1, (p + 1) & 1);   // into buffer of p-1

        if (rv) {
            const float* wb = smem + (p & 1) * SLABF + (lane << 2);
            const bool tap0 = (i < 7), tap1 = (i >= 1);
#pragma unroll
            for (int c = 0; c < 4; ++c) {
                if (c > 0) {
                    xf0 = *reinterpret_cast<const float4*>(xr + (c << 7));
                    xf1 = *reinterpret_cast<const float4*>(
                        xr + (size_t)SSEQ * EE + (c << 7));
                }
                unsigned long long pk[4];
                pk[0] = pack2(xf0.x, xf1.x);
                pk[1] = pack2(xf0.y, xf1.y);
                pk[2] = pack2(xf0.z, xf1.z);
                pk[3] = pack2(xf0.w, xf1.w);

                if (tap0) {
#pragma unroll
                    for (int v = 0; v < 7; ++v) {
                        const float4 wv = *reinterpret_cast<const float4*>(
                            wb + v * HALF + (c << 7));          // LDS.128
                        ffma2(acc[0][v], pack_dup(wv.x), pk[0]);
                        ffma2(acc[0][v], pack_dup(wv.y), pk[1]);
                        ffma2(acc[0][v], pack_dup(wv.z), pk[2]);
                        ffma2(acc[0][v], pack_dup(wv.w), pk[3]);
                    }
                }
                if (tap1) {
#pragma unroll
                    for (int v = 0; v < 7; ++v) {
                        const float4 wv = *reinterpret_cast<const float4*>(
                            wb + (7 + v) * HALF + (c << 7));
                        ffma2(acc[1][v], pack_dup(wv.x), pk[0]);
                        ffma2(acc[1][v], pack_dup(wv.y), pk[1]);
                        ffma2(acc[1][v], pack_dup(wv.z), pk[2]);
                        ffma2(acc[1][v], pack_dup(wv.w), pk[3]);
                    }
                }
            }
        }
    }

    // Lane reduction (halves = the 2 batches stay separate), publish pairs.
#pragma unroll
    for (int tt = 0; tt < 2; ++tt)
#pragma unroll
        for (int v = 0; v < 7; ++v) {
            unsigned long long s = acc[tt][v];
#pragma unroll
            for (int o = 16; o > 0; o >>= 1)
                s = add2(s, shfl_xor_u64(s, o));
            if (lane == 0)
                s_part[warp * 14 + tt * 7 + v] = s;
        }
    __syncthreads();

    // ------------------------------------------------------------------
    // Step 2: warp owns batches (2*warp, 2*warp+1), both t's, 8 rows, full e.
    // Batch sb was accumulated by warp sb>>1 in half sb&1.
    // ------------------------------------------------------------------
    const int sb0 = warp << 1;
    unsigned long long gg[2][7][2];       // [tt][tap][bb] gate, duplicated
#pragma unroll
    for (int bb = 0; bb < 2; ++bb) {
        const int sb = sb0 + bb;
#pragma unroll
        for (int tt = 0; tt < 2; ++tt)
#pragma unroll
            for (int v = 0; v < 7; ++v) {
                const float z =
                    s_partf[((sb >> 1) * 14 + tt * 7 + v) * 2 + (sb & 1)]
                    + bias[(t0 + tt) * WW + v];
                gg[tt][v][bb] = pack_dup(1.0f / (1.0f + __expf(-z)));
            }
    }

#pragma unroll
    for (int c = 0; c < 8; ++c) {
        const int e = (c << 7) + (lane << 2);
        const float* xe = x + (size_t)sb0 * SSEQ * EE + e;
        unsigned long long o[2][2][2];
#pragma unroll
        for (int tt = 0; tt < 2; ++tt)
#pragma unroll
            for (int bb = 0; bb < 2; ++bb) {
                o[tt][bb][0] = 0ull; o[tt][bb][1] = 0ull;
            }
#pragma unroll
        for (int i = 0; i < 8; ++i) {
            const int r = t0 - 3 + i;
            if (r >= 0 && r < SSEQ) {
                const ulonglong2 xA = *reinterpret_cast<const ulonglong2*>(
                    xe + (size_t)r * EE);
                const ulonglong2 xB = *reinterpret_cast<const ulonglong2*>(
                    xe + (size_t)(SSEQ + r) * EE);
                if (i < 7) {
                    ffma2(o[0][0][0], gg[0][i][0], xA.x);
                    ffma2(o[0][0][1], gg[0][i][0], xA.y);
                    ffma2(o[0][1][0], gg[0][i][1], xB.x);
                    ffma2(o[0][1][1], gg[0][i][1], xB.y);
                }
                if (i >= 1) {
                    ffma2(o[1][0][0], gg[1][i - 1][0], xA.x);
                    ffma2(o[1][0][1], gg[1][i - 1][0], xA.y);
                    ffma2(o[1][1][0], gg[1][i - 1][1], xB.x);
                    ffma2(o[1][1][1], gg[1][i - 1][1], xB.y);
                }
            }
        }
#pragma unroll
        for (int tt = 0; tt < 2; ++tt)
#pragma unroll
            for (int bb = 0; bb < 2; ++bb) {
                const float2 p0 = unpack2(o[tt][bb][0]);
                const float2 p1 = unpack2(o[tt][bb][1]);
                float4 ov;
                ov.x = tanh_ap(p0.x);
                ov.y = tanh_ap(p0.y);
                ov.z = tanh_ap(p1.x);
                ov.w = tanh_ap(p1.y);
                *reinterpret_cast<float4*>(
                    out + ((size_t)(sb0 + bb) * SSEQ + (tt ? t1 : t0)) * EE + e)
                    = ov;
            }
    }
}

extern "C" void kernel_launch(void* const* d_in, const int* in_sizes, int n_in,
                              void* d_out, int out_size) {
    const float* x    = (const float*)d_in[0];
    const float* wgt  = (const float*)d_in[1];
    const float* bias = (const float*)d_in[2];
    float* out        = (float*)d_out;

    static bool attr_set = false;
    if (!attr_set) {
        cudaFuncSetAttribute(soft_reorder_kernel,
                             cudaFuncAttributeMaxDynamicSharedMemorySize,
                             SMEM_BYTES);
        attr_set = true;
    }
    soft_reorder_kernel<<<SSEQ / 2, 256, SMEM_BYTES>>>(x, wgt, bias, out);
}

// round 14
// speedup vs baseline: 1.3739x; 1.0183x over previous
#include <cuda_runtime.h>
#include <cstdint>

// SoftReordering, R13: R8 structure (nb=4, weight-LDS redundancy 4, occ 2)
//   with FULL-ROW slab phases: 8 phases of 14 rows x 1024 floats (56KB),
//   NBUF=2 (112KB smem), halving cp_wait+barrier count and doubling the
//   compute window per staged slab. Logit partials overlaid into slab buf 0
//   after the final phase (dead by then) to stay inside the 2-CTA smem
//   budget (2 x 14 x 8KB granules = 224KB <= 228KB).

#define SSEQ 1024
#define EE   1024
#define WW   7
#define WE   7168
#define SLABF (14 * EE)              // full-row slab: 14 rows x 1024 = 56KB
#define NBUF 2
#define SMEM_BYTES (NBUF * SLABF * 4)   // 114688 = 14 x 8KB granules

__device__ __forceinline__ uint32_t smem_u32(const void* p) {
    uint32_t a;
    asm("{ .reg .u64 t; cvta.to.shared.u64 t, %1; cvt.u32.u64 %0, t; }"
        : "=r"(a) : "l"(p));
    return a;
}
__device__ __forceinline__ void cp_async16(uint32_t saddr, const void* gptr) {
    asm volatile("cp.async.cg.shared.global [%0], [%1], 16;"
                 :: "r"(saddr), "l"(gptr));
}
__device__ __forceinline__ void cp_commit() {
    asm volatile("cp.async.commit_group;");
}
template <int N>
__device__ __forceinline__ void cp_wait() {
    asm volatile("cp.async.wait_group %0;" :: "n"(N));
}
__device__ __forceinline__ void ffma2(unsigned long long& d,
                                      unsigned long long a,
                                      unsigned long long b) {
    asm("fma.rn.f32x2 %0, %1, %2, %3;" : "=l"(d) : "l"(a), "l"(b), "l"(d));
}
__device__ __forceinline__ unsigned long long pack2(float lo, float hi) {
    unsigned long long p;
    asm("mov.b64 %0, {%1, %2};" : "=l"(p) : "f"(lo), "f"(hi));
    return p;
}
__device__ __forceinline__ unsigned long long pack_dup(float g) {
    unsigned long long p;
    asm("mov.b64 %0, {%1, %1};" : "=l"(p) : "f"(g));
    return p;
}
__device__ __forceinline__ float2 unpack2(unsigned long long v) {
    float2 r;
    asm("mov.b64 {%0, %1}, %2;" : "=f"(r.x), "=f"(r.y) : "l"(v));
    return r;
}
__device__ __forceinline__ unsigned long long add2(unsigned long long a,
                                                   unsigned long long b) {
    unsigned long long d;
    asm("add.rn.f32x2 %0, %1, %2;" : "=l"(d) : "l"(a), "l"(b));
    return d;
}
__device__ __forceinline__ unsigned long long shfl_xor_u64(unsigned long long v,
                                                           int m) {
    uint32_t lo = (uint32_t)v, hi = (uint32_t)(v >> 32);
    lo = __shfl_xor_sync(0xffffffffu, lo, m);
    hi = __shfl_xor_sync(0xffffffffu, hi, m);
    return ((unsigned long long)hi << 32) | lo;
}
__device__ __forceinline__ float tanh_ap(float x) {
    float r;
    asm("tanh.approx.f32 %0, %1;" : "=f"(r) : "f"(x));
    return r;
}

__global__ void __launch_bounds__(256, 2)
soft_reorder_kernel(const float* __restrict__ x,
                    const float* __restrict__ wgt,
                    const float* __restrict__ bias,
                    float* __restrict__ out) {
    extern __shared__ float smem[];
    // Partials overlay slab buffer 0 (dead after final phase).
    unsigned long long* s_part = reinterpret_cast<unsigned long long*>(smem);
    const float* s_partf = smem;

    const int t0   = (int)blockIdx.x * 2;
    const int t1   = t0 + 1;
    const int tid  = threadIdx.x;
    const int lane = tid & 31;
    const int warp = tid >> 5;
    const int ec   = warp & 1;            // e-half (0: [0,512), 1: [512,1024))
    const int b0   = (warp >> 1) << 2;    // batch group base (4 batches)
    const uint32_t sbase = smem_u32(smem);

    // Slab for row-iter i: rows 0-6 = weight[t0, v, i*E + :E] (tap i, if i<7),
    //                      rows 7-13 = weight[t1, v, (i-1)*E + :E] (if i>=1).
    auto stage = [&](int i, int buf) {
        const int r = t0 - 3 + i;
        if (r >= 0 && r < SSEQ) {
            const uint32_t dst = sbase + (uint32_t)buf * (SLABF * 4);
#pragma unroll
            for (int k = 0; k < 14; ++k) {
                const int j   = tid + (k << 8);     // 0..3583 (float4 index)
                const int row = j >> 8;             // 0..13
                const int col = (j & 255) << 2;     // float offset in row
                const float* src;
                bool ok;
                if (row < 7) {
                    ok  = (i < 7);
                    src = wgt + (size_t)(t0 * WW + row) * WE
                              + (size_t)i * EE + col;
                } else {
                    ok  = (i >= 1);
                    src = wgt + (size_t)(t1 * WW + (row - 7)) * WE
                              + (size_t)(i - 1) * EE + col;
                }
                if (ok)
                    cp_async16(dst + (uint32_t)(row * EE + col) * 4, src);
            }
        }
        cp_commit();
    };

    // ------------------------------------------------------------------
    // Step 1: acc[tt][v][pair], batch pairs (b0+2p, b0+2p+1) packed f32x2.
    // ------------------------------------------------------------------
    unsigned long long acc[2][7][2];
#pragma unroll
    for (int tt = 0; tt < 2; ++tt)
#pragma unroll
        for (int v = 0; v < 7; ++v)
#pragma unroll
            for (int pr = 0; pr < 2; ++pr)
                acc[tt][v][pr] = 0ull;

    stage(0, 0);
    for (int i = 0; i < 8; ++i) {
        const int r = t0 - 3 + i;
        const bool rv = (r >= 0 && r < SSEQ);

        // Front-issue first 2 c-chunks of x (8 LDG.128): latency hides under
        // the cp_wait + barrier below.
        const float* xr = x + ((size_t)b0 * SSEQ + r) * EE
                            + ec * 512 + (lane << 2);
        float4 xv[2][4];
        if (rv) {
#pragma unroll
            for (int c = 0; c < 2; ++c)
#pragma unroll
                for (int bb = 0; bb < 4; ++bb)
                    xv[c][bb] = *reinterpret_cast<const float4*>(
                        xr + (size_t)bb * SSEQ * EE + (c << 7));
        }

        cp_wait<0>();          // slab i complete (sole pending group)
        __syncthreads();       // slab i visible; all warps done with i-1
        if (i + 1 < 8) stage(i + 1, (i + 1) & 1);   // into buffer of i-1

        if (rv) {
            const float* wb = smem + (i & 1) * SLABF + ec * 512 + (lane << 2);
            const bool tap0 = (i < 7), tap1 = (i >= 1);
#pragma unroll
            for (int c = 0; c < 4; ++c) {
                float4 xc[4];
                if (c < 2) {
#pragma unroll
                    for (int bb = 0; bb < 4; ++bb) xc[bb] = xv[c][bb];
                } else {
#pragma unroll
                    for (int bb = 0; bb < 4; ++bb)
                        xc[bb] = *reinterpret_cast<const float4*>(
                            xr + (size_t)bb * SSEQ * EE + (c << 7));
                }
                unsigned long long pk[2][4];
                pk[0][0] = pack2(xc[0].x, xc[1].x);
                pk[1][0] = pack2(xc[2].x, xc[3].x);
                pk[0][1] = pack2(xc[0].y, xc[1].y);
                pk[1][1] = pack2(xc[2].y, xc[3].y);
                pk[0][2] = pack2(xc[0].z, xc[1].z);
                pk[1][2] = pack2(xc[2].z, xc[3].z);
                pk[0][3] = pack2(xc[0].w, xc[1].w);
                pk[1][3] = pack2(xc[2].w, xc[3].w);

                if (tap0) {
#pragma unroll
                    for (int v = 0; v < 7; ++v) {
                        const float4 wv = *reinterpret_cast<const float4*>(
                            wb + v * EE + (c << 7));            // LDS.128
                        const float* wk = &wv.x;
#pragma unroll
                        for (int k = 0; k < 4; ++k) {
                            const unsigned long long dw = pack_dup(wk[k]);
                            ffma2(acc[0][v][0], dw, pk[0][k]);
                            ffma2(acc[0][v][1], dw, pk[1][k]);
                        }
                    }
                }
                if (tap1) {
#pragma unroll
                    for (int v = 0; v < 7; ++v) {
                        const float4 wv = *reinterpret_cast<const float4*>(
                            wb + (7 + v) * EE + (c << 7));
                        const float* wk = &wv.x;
#pragma unroll
                        for (int k = 0; k < 4; ++k) {
                            const unsigned long long dw = pack_dup(wk[k]);
                            ffma2(acc[1][v][0], dw, pk[0][k]);
                            ffma2(acc[1][v][1], dw, pk[1][k]);
                        }
                    }
                }
            }
        }
    }

    // Lane reduction (packed halves = batch 2p / 2p+1), publish to the
    // overlay region (slab buf 0: last read at i=6, retired by i=7 barrier).
#pragma unroll
    for (int tt = 0; tt < 2; ++tt)
#pragma unroll
        for (int v = 0; v < 7; ++v)
#pragma unroll
            for (int pr = 0; pr < 2; ++pr) {
                unsigned long long s = acc[tt][v][pr];
#pragma unroll
                for (int o = 16; o > 0; o >>= 1)
                    s = add2(s, shfl_xor_u64(s, o));
                if (lane == 0)
                    s_part[(((ec << 2) | (warp >> 1)) * 14 + tt * 7 + v) * 2 + pr] = s;
            }
    __syncthreads();

    // ------------------------------------------------------------------
    // Step 2: warp owns batches (2*warp, 2*warp+1), both t's, 8 rows, full e.
    // ------------------------------------------------------------------
    const int sb0 = warp << 1;
    unsigned long long gg[2][7][2];       // [tt][tap][bb] gate, duplicated
#pragma unroll
    for (int bb = 0; bb < 2; ++bb) {
        const int sb  = sb0 + bb;
        const int bg2 = sb >> 2;
        const int pr  = (sb >> 1) & 1;
        const int hf  = sb & 1;
#pragma unroll
        for (int tt = 0; tt < 2; ++tt)
#pragma unroll
            for (int v = 0; v < 7; ++v) {
                const int base = ((bg2 * 14 + tt * 7 + v) * 2 + pr) * 2 + hf;
                const float z = s_partf[base]
                              + s_partf[(4 * 14 * 2) * 2 + base]   // ec=1 block
                              + bias[(t0 + tt) * WW + v];
                gg[tt][v][bb] = pack_dup(1.0f / (1.0f + __expf(-z)));
            }
    }

#pragma unroll
    for (int c = 0; c < 8; ++c) {
        const int e = (c << 7) + (lane << 2);
        const float* xe = x + (size_t)sb0 * SSEQ * EE + e;
        unsigned long long o[2][2][2];
#pragma unroll
        for (int tt = 0; tt < 2; ++tt)
#pragma unroll
            for (int bb = 0; bb < 2; ++bb) {
                o[tt][bb][0] = 0ull; o[tt][bb][1] = 0ull;
            }
#pragma unroll
        for (int i = 0; i < 8; ++i) {
            const int r = t0 - 3 + i;
            if (r >= 0 && r < SSEQ) {
                const ulonglong2 xA = *reinterpret_cast<const ulonglong2*>(
                    xe + (size_t)r * EE);
                const ulonglong2 xB = *reinterpret_cast<const ulonglong2*>(
                    xe + (size_t)(SSEQ + r) * EE);
                if (i < 7) {
                    ffma2(o[0][0][0], gg[0][i][0], xA.x);
                    ffma2(o[0][0][1], gg[0][i][0], xA.y);
                    ffma2(o[0][1][0], gg[0][i][1], xB.x);
                    ffma2(o[0][1][1], gg[0][i][1], xB.y);
                }
                if (i >= 1) {
                    ffma2(o[1][0][0], gg[1][i - 1][0], xA.x);
                    ffma2(o[1][0][1], gg[1][i - 1][0], xA.y);
                    ffma2(o[1][1][0], gg[1][i - 1][1], xB.x);
                    ffma2(o[1][1][1], gg[1][i - 1][1], xB.y);
                }
            }
        }
#pragma unroll
        for (int tt = 0; tt < 2; ++tt)
#pragma unroll
            for (int bb = 0; bb < 2; ++bb) {
                const float2 p0 = unpack2(o[tt][bb][0]);
                const float2 p1 = unpack2(o[tt][bb][1]);
                float4 ov;
                ov.x = tanh_ap(p0.x);
                ov.y = tanh_ap(p0.y);
                ov.z = tanh_ap(p1.x);
                ov.w = tanh_ap(p1.y);
                *reinterpret_cast<float4*>(
                    out + ((size_t)(sb0 + bb) * SSEQ + (tt ? t1 : t0)) * EE + e)
                    = ov;
            }
    }
}

extern "C" void kernel_launch(void* const* d_in, const int* in_sizes, int n_in,
                              void* d_out, int out_size) {
    const float* x    = (const float*)d_in[0];
    const float* wgt  = (const float*)d_in[1];
    const float* bias = (const float*)d_in[2];
    float* out        = (float*)d_out;

    static bool attr_set = false;
    if (!attr_set) {
        cudaFuncSetAttribute(soft_reorder_kernel,
                             cudaFuncAttributeMaxDynamicSharedMemorySize,
                             SMEM_BYTES);
        attr_set = true;
    }
    soft_reorder_kernel<<<SSEQ / 2, 256, SMEM_BYTES>>>(x, wgt, bias, out);
}

// round 15
// speedup vs baseline: 1.3916x; 1.0128x over previous
#include <cuda_runtime.h>
#include <cstdint>

// SoftReordering, R14: R8 (best, 104.9us) + deeper cp.async pipeline.
//   NBUF 3 -> 4 (stage p+3, cp_wait<2>): each 28KB slab gets ~3 compute
//   phases of DRAM window instead of ~2, absorbing bandwidth jitter.
//   Output stores use st.global.cs (evict-first; out is never re-read)
//   to protect the x window in L2. Everything else identical to R8.

#define SSEQ 1024
#define EE   1024
#define WW   7
#define WE   7168
#define HALF 512                     // floats per phase (e-half)
#define SLABF (14 * HALF)            // 28KB slab: 14 (t,v) rows x 512
#define NBUF 4
#define PART_OFF (NBUF * SLABF)      // float offset of partials
#define PART_FLOATS (2 * 4 * 2 * 7 * 2 * 2)   // ec,bg,tt,v,pair,half = 448
#define SMEM_BYTES ((NBUF * SLABF + PART_FLOATS) * 4)   // 116480

__device__ __forceinline__ uint32_t smem_u32(const void* p) {
    uint32_t a;
    asm("{ .reg .u64 t; cvta.to.shared.u64 t, %1; cvt.u32.u64 %0, t; }"
        : "=r"(a) : "l"(p));
    return a;
}
__device__ __forceinline__ void cp_async16(uint32_t saddr, const void* gptr) {
    asm volatile("cp.async.cg.shared.global [%0], [%1], 16;"
                 :: "r"(saddr), "l"(gptr));
}
__device__ __forceinline__ void cp_commit() {
    asm volatile("cp.async.commit_group;");
}
template <int N>
__device__ __forceinline__ void cp_wait() {
    asm volatile("cp.async.wait_group %0;" :: "n"(N));
}
__device__ __forceinline__ void ffma2(unsigned long long& d,
                                      unsigned long long a,
                                      unsigned long long b) {
    asm("fma.rn.f32x2 %0, %1, %2, %3;" : "=l"(d) : "l"(a), "l"(b), "l"(d));
}
__device__ __forceinline__ unsigned long long pack2(float lo, float hi) {
    unsigned long long p;
    asm("mov.b64 %0, {%1, %2};" : "=l"(p) : "f"(lo), "f"(hi));
    return p;
}
__device__ __forceinline__ unsigned long long pack_dup(float g) {
    unsigned long long p;
    asm("mov.b64 %0, {%1, %1};" : "=l"(p) : "f"(g));
    return p;
}
__device__ __forceinline__ float2 unpack2(unsigned long long v) {
    float2 r;
    asm("mov.b64 {%0, %1}, %2;" : "=f"(r.x), "=f"(r.y) : "l"(v));
    return r;
}
__device__ __forceinline__ unsigned long long add2(unsigned long long a,
                                                   unsigned long long b) {
    unsigned long long d;
    asm("add.rn.f32x2 %0, %1, %2;" : "=l"(d) : "l"(a), "l"(b));
    return d;
}
__device__ __forceinline__ unsigned long long shfl_xor_u64(unsigned long long v,
                                                           int m) {
    uint32_t lo = (uint32_t)v, hi = (uint32_t)(v >> 32);
    lo = __shfl_xor_sync(0xffffffffu, lo, m);
    hi = __shfl_xor_sync(0xffffffffu, hi, m);
    return ((unsigned long long)hi << 32) | lo;
}
__device__ __forceinline__ float tanh_ap(float x) {
    float r;
    asm("tanh.approx.f32 %0, %1;" : "=f"(r) : "f"(x));
    return r;
}
__device__ __forceinline__ void stg_cs(float* p, float4 v) {
    asm volatile("st.global.cs.v4.f32 [%0], {%1, %2, %3, %4};"
                 :: "l"(p), "f"(v.x), "f"(v.y), "f"(v.z), "f"(v.w)
                 : "memory");
}

__global__ void __launch_bounds__(256, 2)
soft_reorder_kernel(const float* __restrict__ x,
                    const float* __restrict__ wgt,
                    const float* __restrict__ bias,
                    float* __restrict__ out) {
    extern __shared__ float smem[];
    unsigned long long* s_part =
        reinterpret_cast<unsigned long long*>(smem + PART_OFF);
    const float* s_partf = smem + PART_OFF;

    const int t0   = (int)blockIdx.x * 2;
    const int t1   = t0 + 1;
    const int tid  = threadIdx.x;
    const int lane = tid & 31;
    const int warp = tid >> 5;
    const int ec   = warp & 1;            // e-chunk (0: [0,256), 1: [256,512))
    const int b0   = (warp >> 1) << 2;    // batch group base (4 batches)
    const uint32_t sbase = smem_u32(smem);

    // Slab phase p = i*2+h: rows 0-6 = weight[t0, v, i*E + h*HALF ..],
    //                       rows 7-13 = weight[t1, v, (i-1)*E + h*HALF ..].
    auto stage = [&](int p, int buf) {
        const int i = p >> 1, h = p & 1;
        const int r = t0 - 3 + i;
        if (r >= 0 && r < SSEQ) {
            const uint32_t dst = sbase + (uint32_t)buf * (SLABF * 4);
#pragma unroll
            for (int k = 0; k < 7; ++k) {
                const int j   = tid + (k << 8);     // 0..1791
                const int row = j >> 7;             // 0..13
                const int col = (j & 127) << 2;
                const float* src;
                bool ok;
                if (row < 7) {
                    ok  = (i < 7);
                    src = wgt + (size_t)(t0 * WW + row) * WE
                              + (size_t)i * EE + h * HALF + col;
                } else {
                    ok  = (i >= 1);
                    src = wgt + (size_t)(t1 * WW + (row - 7)) * WE
                              + (size_t)(i - 1) * EE + h * HALF + col;
                }
                if (ok)
                    cp_async16(dst + (uint32_t)(row * HALF + col) * 4, src);
            }
        }
        cp_commit();
    };

    // ------------------------------------------------------------------
    // Step 1: acc[tt][v][pair] packed over batch pairs (b0+2p, b0+2p+1).
    // ------------------------------------------------------------------
    unsigned long long acc[2][7][2];
#pragma unroll
    for (int tt = 0; tt < 2; ++tt)
#pragma unroll
        for (int v = 0; v < 7; ++v)
#pragma unroll
            for (int pr = 0; pr < 2; ++pr)
                acc[tt][v][pr] = 0ull;

    stage(0, 0);
    stage(1, 1);
    stage(2, 2);
    for (int p = 0; p < 16; ++p) {
        const int i = p >> 1, h = p & 1;
        const int r = t0 - 3 + i;
        const bool rv = (r >= 0 && r < SSEQ);

        // Front-issue x loads: overlap LDG latency with cp_wait + barrier.
        float4 xv[2][4];
        if (rv) {
            const float* xr = x + ((size_t)b0 * SSEQ + r) * EE
                                + h * HALF + ec * 256 + (lane << 2);
#pragma unroll
            for (int c = 0; c < 2; ++c)
#pragma unroll
                for (int bb = 0; bb < 4; ++bb)
                    xv[c][bb] = *reinterpret_cast<const float4*>(
                        xr + (size_t)bb * SSEQ * EE + (c << 7));
        }

        // Groups pending after prologue/steady-state staging: p, p+1, p+2.
        // cp_wait<2> retires everything but the 2 newest -> slab p complete.
        if (p < 14) cp_wait<2>(); else if (p == 14) cp_wait<1>(); else cp_wait<0>();
        __syncthreads();                    // slab p visible; p-1 readers done
        if (p + 3 < 16) stage(p + 3, (p + 3) & 3);   // buffer of p-1

        if (rv) {
            const float* wb = smem + (p & 3) * SLABF + ec * 256 + (lane << 2);
            const bool tap0 = (i < 7), tap1 = (i >= 1);
#pragma unroll
            for (int c = 0; c < 2; ++c) {
                unsigned long long pk[2][4];
#pragma unroll
                for (int k = 0; k < 4; ++k) {
                    const float* a0 = &xv[c][0].x;
                    const float* a1 = &xv[c][1].x;
                    const float* a2 = &xv[c][2].x;
                    const float* a3 = &xv[c][3].x;
                    pk[0][k] = pack2(a0[k], a1[k]);
                    pk[1][k] = pack2(a2[k], a3[k]);
                }
                if (tap0) {
#pragma unroll
                    for (int v = 0; v < 7; ++v) {
                        const float4 wv = *reinterpret_cast<const float4*>(
                            wb + v * HALF + (c << 7));          // LDS.128
                        const float* wk = &wv.x;
#pragma unroll
                        for (int k = 0; k < 4; ++k) {
                            const unsigned long long dw = pack_dup(wk[k]);
                            ffma2(acc[0][v][0], dw, pk[0][k]);
                            ffma2(acc[0][v][1], dw, pk[1][k]);
                        }
                    }
                }
                if (tap1) {
#pragma unroll
                    for (int v = 0; v < 7; ++v) {
                        const float4 wv = *reinterpret_cast<const float4*>(
                            wb + (7 + v) * HALF + (c << 7));
                        const float* wk = &wv.x;
#pragma unroll
                        for (int k = 0; k < 4; ++k) {
                            const unsigned long long dw = pack_dup(wk[k]);
                            ffma2(acc[1][v][0], dw, pk[0][k]);
                            ffma2(acc[1][v][1], dw, pk[1][k]);
                        }
                    }
                }
            }
        }
    }

    // Lane reduction (packed halves stay separate: lo = batch 2p, hi = 2p+1),
    // then publish per-(ec,bg) partials to smem.
#pragma unroll
    for (int tt = 0; tt < 2; ++tt)
#pragma unroll
        for (int v = 0; v < 7; ++v)
#pragma unroll
            for (int pr = 0; pr < 2; ++pr) {
                unsigned long long s = acc[tt][v][pr];
#pragma unroll
                for (int o = 16; o > 0; o >>= 1)
                    s = add2(s, shfl_xor_u64(s, o));
                if (lane == 0)
                    s_part[(((ec << 2) | (warp >> 1)) * 14 + tt * 7 + v) * 2 + pr] = s;
            }
    __syncthreads();

    // ------------------------------------------------------------------
    // Step 2: warp owns batches (2*warp, 2*warp+1), both t's, 8 rows, full e.
    // ------------------------------------------------------------------
    const int sb0 = warp << 1;
    unsigned long long gg[2][7][2];       // [tt][tap][bb] gate, duplicated
#pragma unroll
    for (int bb = 0; bb < 2; ++bb) {
        const int sb  = sb0 + bb;
        const int bg2 = sb >> 2;
        const int pr  = (sb >> 1) & 1;
        const int hf  = sb & 1;
#pragma unroll
        for (int tt = 0; tt < 2; ++tt)
#pragma unroll
            for (int v = 0; v < 7; ++v) {
                const int base = ((bg2 * 14 + tt * 7 + v) * 2 + pr) * 2 + hf;
                const float z = s_partf[base]
                              + s_partf[(4 * 14 * 2) * 2 + base]   // ec=1 block
                              + bias[(t0 + tt) * WW + v];
                gg[tt][v][bb] = pack_dup(1.0f / (1.0f + __expf(-z)));
            }
    }

#pragma unroll
    for (int c = 0; c < 8; ++c) {
        const int e = (c << 7) + (lane << 2);
        const float* xe = x + (size_t)sb0 * SSEQ * EE + e;
        unsigned long long o[2][2][2];
#pragma unroll
        for (int tt = 0; tt < 2; ++tt)
#pragma unroll
            for (int bb = 0; bb < 2; ++bb) {
                o[tt][bb][0] = 0ull; o[tt][bb][1] = 0ull;
            }
#pragma unroll
        for (int i = 0; i < 8; ++i) {
            const int r = t0 - 3 + i;
            if (r >= 0 && r < SSEQ) {
                const ulonglong2 xA = *reinterpret_cast<const ulonglong2*>(
                    xe + (size_t)r * EE);
                const ulonglong2 xB = *reinterpret_cast<const ulonglong2*>(
                    xe + (size_t)(SSEQ + r) * EE);
                if (i < 7) {
                    ffma2(o[0][0][0], gg[0][i][0], xA.x);
                    ffma2(o[0][0][1], gg[0][i][0], xA.y);
                    ffma2(o[0][1][0], gg[0][i][1], xB.x);
                    ffma2(o[0][1][1], gg[0][i][1], xB.y);
                }
                if (i >= 1) {
                    ffma2(o[1][0][0], gg[1][i - 1][0], xA.x);
                    ffma2(o[1][0][1], gg[1][i - 1][0], xA.y);
                    ffma2(o[1][1][0], gg[1][i - 1][1], xB.x);
                    ffma2(o[1][1][1], gg[1][i - 1][1], xB.y);
                }
            }
        }
#pragma unroll
        for (int tt = 0; tt < 2; ++tt)
#pragma unroll
            for (int bb = 0; bb < 2; ++bb) {
                const float2 p0 = unpack2(o[tt][bb][0]);
                const float2 p1 = unpack2(o[tt][bb][1]);
                float4 ov;
                ov.x = tanh_ap(p0.x);
                ov.y = tanh_ap(p0.y);
                ov.z = tanh_ap(p1.x);
                ov.w = tanh_ap(p1.y);
                stg_cs(out + ((size_t)(sb0 + bb) * SSEQ + (tt ? t1 : t0)) * EE + e,
                       ov);
            }
    }
}

extern "C" void kernel_launch(void* const* d_in, const int* in_sizes, int n_in,
                              void* d_out, int out_size) {
    const float* x    = (const float*)d_in[0];
    const float* wgt  = (const float*)d_in[1];
    const float* bias = (const float*)d_in[2];
    float* out        = (float*)d_out;

    static bool attr_set = false;
    if (!attr_set) {
        cudaFuncSetAttribute(soft_reorder_kernel,
                             cudaFuncAttributeMaxDynamicSharedMemorySize,
                             SMEM_BYTES);
        attr_set = true;
    }
    soft_reorder_kernel<<<SSEQ / 2, 256, SMEM_BYTES>>>(x, wgt, bias, out);
}

// round 16
// speedup vs baseline: 1.5989x; 1.1490x over previous
#include <cuda_runtime.h>
#include <cstdint>

// SoftReordering, R15: R14's depth-3 pipeline with the smem-granularity bug
//   fixed. NBUF=4 slabs ONLY (114688 B = exactly 14 x 8KB granules; 2 CTAs
//   = 229376 <= 228KB -> occupancy 2 restored, which R14 silently lost to
//   granule rounding -> 1 CTA/SM). Logit partials overlay slab buffer 0
//   (last read at phase 12, retired by the phase-13 barrier; written only
//   after the phase-15 barrier). Otherwise identical to R8/R14: nb=4
//   batch-packed f32x2, weight-LDS redundancy 4, st.global.cs outputs.

#define SSEQ 1024
#define EE   1024
#define WW   7
#define WE   7168
#define HALF 512                     // floats per phase (e-half)
#define SLABF (14 * HALF)            // 28KB slab: 14 (t,v) rows x 512
#define NBUF 4
#define SMEM_BYTES (NBUF * SLABF * 4)   // 114688 = 14 granules exactly

__device__ __forceinline__ uint32_t smem_u32(const void* p) {
    uint32_t a;
    asm("{ .reg .u64 t; cvta.to.shared.u64 t, %1; cvt.u32.u64 %0, t; }"
        : "=r"(a) : "l"(p));
    return a;
}
__device__ __forceinline__ void cp_async16(uint32_t saddr, const void* gptr) {
    asm volatile("cp.async.cg.shared.global [%0], [%1], 16;"
                 :: "r"(saddr), "l"(gptr));
}
__device__ __forceinline__ void cp_commit() {
    asm volatile("cp.async.commit_group;");
}
template <int N>
__device__ __forceinline__ void cp_wait() {
    asm volatile("cp.async.wait_group %0;" :: "n"(N));
}
__device__ __forceinline__ void ffma2(unsigned long long& d,
                                      unsigned long long a,
                                      unsigned long long b) {
    asm("fma.rn.f32x2 %0, %1, %2, %3;" : "=l"(d) : "l"(a), "l"(b), "l"(d));
}
__device__ __forceinline__ unsigned long long pack2(float lo, float hi) {
    unsigned long long p;
    asm("mov.b64 %0, {%1, %2};" : "=l"(p) : "f"(lo), "f"(hi));
    return p;
}
__device__ __forceinline__ unsigned long long pack_dup(float g) {
    unsigned long long p;
    asm("mov.b64 %0, {%1, %1};" : "=l"(p) : "f"(g));
    return p;
}
__device__ __forceinline__ float2 unpack2(unsigned long long v) {
    float2 r;
    asm("mov.b64 {%0, %1}, %2;" : "=f"(r.x), "=f"(r.y) : "l"(v));
    return r;
}
__device__ __forceinline__ unsigned long long add2(unsigned long long a,
                                                   unsigned long long b) {
    unsigned long long d;
    asm("add.rn.f32x2 %0, %1, %2;" : "=l"(d) : "l"(a), "l"(b));
    return d;
}
__device__ __forceinline__ unsigned long long shfl_xor_u64(unsigned long long v,
                                                           int m) {
    uint32_t lo = (uint32_t)v, hi = (uint32_t)(v >> 32);
    lo = __shfl_xor_sync(0xffffffffu, lo, m);
    hi = __shfl_xor_sync(0xffffffffu, hi, m);
    return ((unsigned long long)hi << 32) | lo;
}
__device__ __forceinline__ float tanh_ap(float x) {
    float r;
    asm("tanh.approx.f32 %0, %1;" : "=f"(r) : "f"(x));
    return r;
}
__device__ __forceinline__ void stg_cs(float* p, float4 v) {
    asm volatile("st.global.cs.v4.f32 [%0], {%1, %2, %3, %4};"
                 :: "l"(p), "f"(v.x), "f"(v.y), "f"(v.z), "f"(v.w)
                 : "memory");
}

__global__ void __launch_bounds__(256, 2)
soft_reorder_kernel(const float* __restrict__ x,
                    const float* __restrict__ wgt,
                    const float* __restrict__ bias,
                    float* __restrict__ out) {
    extern __shared__ float smem[];
    // Partials overlay slab buffer 0 (dead: last read phase 12, retired by
    // the phase-13 barrier; written only after the phase-15 barrier).
    unsigned long long* s_part = reinterpret_cast<unsigned long long*>(smem);
    const float* s_partf = smem;

    const int t0   = (int)blockIdx.x * 2;
    const int t1   = t0 + 1;
    const int tid  = threadIdx.x;
    const int lane = tid & 31;
    const int warp = tid >> 5;
    const int ec   = warp & 1;            // e-chunk (0: [0,256), 1: [256,512))
    const int b0   = (warp >> 1) << 2;    // batch group base (4 batches)
    const uint32_t sbase = smem_u32(smem);

    // Slab phase p = i*2+h: rows 0-6 = weight[t0, v, i*E + h*HALF ..],
    //                       rows 7-13 = weight[t1, v, (i-1)*E + h*HALF ..].
    auto stage = [&](int p, int buf) {
        const int i = p >> 1, h = p & 1;
        const int r = t0 - 3 + i;
        if (r >= 0 && r < SSEQ) {
            const uint32_t dst = sbase + (uint32_t)buf * (SLABF * 4);
#pragma unroll
            for (int k = 0; k < 7; ++k) {
                const int j   = tid + (k << 8);     // 0..1791
                const int row = j >> 7;             // 0..13
                const int col = (j & 127) << 2;
                const float* src;
                bool ok;
                if (row < 7) {
                    ok  = (i < 7);
                    src = wgt + (size_t)(t0 * WW + row) * WE
                              + (size_t)i * EE + h * HALF + col;
                } else {
                    ok  = (i >= 1);
                    src = wgt + (size_t)(t1 * WW + (row - 7)) * WE
                              + (size_t)(i - 1) * EE + h * HALF + col;
                }
                if (ok)
                    cp_async16(dst + (uint32_t)(row * HALF + col) * 4, src);
            }
        }
        cp_commit();
    };

    // ------------------------------------------------------------------
    // Step 1: acc[tt][v][pair] packed over batch pairs (b0+2p, b0+2p+1).
    // ------------------------------------------------------------------
    unsigned long long acc[2][7][2];
#pragma unroll
    for (int tt = 0; tt < 2; ++tt)
#pragma unroll
        for (int v = 0; v < 7; ++v)
#pragma unroll
            for (int pr = 0; pr < 2; ++pr)
                acc[tt][v][pr] = 0ull;

    stage(0, 0);
    stage(1, 1);
    stage(2, 2);
    for (int p = 0; p < 16; ++p) {
        const int i = p >> 1, h = p & 1;
        const int r = t0 - 3 + i;
        const bool rv = (r >= 0 && r < SSEQ);

        // Front-issue x loads: overlap LDG latency with cp_wait + barrier.
        float4 xv[2][4];
        if (rv) {
            const float* xr = x + ((size_t)b0 * SSEQ + r) * EE
                                + h * HALF + ec * 256 + (lane << 2);
#pragma unroll
            for (int c = 0; c < 2; ++c)
#pragma unroll
                for (int bb = 0; bb < 4; ++bb)
                    xv[c][bb] = *reinterpret_cast<const float4*>(
                        xr + (size_t)bb * SSEQ * EE + (c << 7));
        }

        // Pending groups before wait: p, p+1, p+2. cp_wait<2> retires all
        // but the 2 newest -> slab p complete.
        if (p < 14) cp_wait<2>(); else if (p == 14) cp_wait<1>(); else cp_wait<0>();
        __syncthreads();                    // slab p visible; p-1 readers done
        if (p + 3 < 16) stage(p + 3, (p + 3) & 3);   // buffer of p-1

        if (rv) {
            const float* wb = smem + (p & 3) * SLABF + ec * 256 + (lane << 2);
            const bool tap0 = (i < 7), tap1 = (i >= 1);
#pragma unroll
            for (int c = 0; c < 2; ++c) {
                unsigned long long pk[2][4];
#pragma unroll
                for (int k = 0; k < 4; ++k) {
                    const float* a0 = &xv[c][0].x;
                    const float* a1 = &xv[c][1].x;
                    const float* a2 = &xv[c][2].x;
                    const float* a3 = &xv[c][3].x;
                    pk[0][k] = pack2(a0[k], a1[k]);
                    pk[1][k] = pack2(a2[k], a3[k]);
                }
                if (tap0) {
#pragma unroll
                    for (int v = 0; v < 7; ++v) {
                        const float4 wv = *reinterpret_cast<const float4*>(
                            wb + v * HALF + (c << 7));          // LDS.128
                        const float* wk = &wv.x;
#pragma unroll
                        for (int k = 0; k < 4; ++k) {
                            const unsigned long long dw = pack_dup(wk[k]);
                            ffma2(acc[0][v][0], dw, pk[0][k]);
                            ffma2(acc[0][v][1], dw, pk[1][k]);
                        }
                    }
                }
                if (tap1) {
#pragma unroll
                    for (int v = 0; v < 7; ++v) {
                        const float4 wv = *reinterpret_cast<const float4*>(
                            wb + (7 + v) * HALF + (c << 7));
                        const float* wk = &wv.x;
#pragma unroll
                        for (int k = 0; k < 4; ++k) {
                            const unsigned long long dw = pack_dup(wk[k]);
                            ffma2(acc[1][v][0], dw, pk[0][k]);
                            ffma2(acc[1][v][1], dw, pk[1][k]);
                        }
                    }
                }
            }
        }
    }

    // Lane reduction (packed halves stay separate: lo = batch 2p, hi = 2p+1),
    // then publish per-(ec,bg) partials to the overlay region (slab buf 0).
#pragma unroll
    for (int tt = 0; tt < 2; ++tt)
#pragma unroll
        for (int v = 0; v < 7; ++v)
#pragma unroll
            for (int pr = 0; pr < 2; ++pr) {
                unsigned long long s = acc[tt][v][pr];
#pragma unroll
                for (int o = 16; o > 0; o >>= 1)
                    s = add2(s, shfl_xor_u64(s, o));
                if (lane == 0)
                    s_part[(((ec << 2) | (warp >> 1)) * 14 + tt * 7 + v) * 2 + pr] = s;
            }
    __syncthreads();

    // ------------------------------------------------------------------
    // Step 2: warp owns batches (2*warp, 2*warp+1), both t's, 8 rows, full e.
    // ------------------------------------------------------------------
    const int sb0 = warp << 1;
    unsigned long long gg[2][7][2];       // [tt][tap][bb] gate, duplicated
#pragma unroll
    for (int bb = 0; bb < 2; ++bb) {
        const int sb  = sb0 + bb;
        const int bg2 = sb >> 2;
        const int pr  = (sb >> 1) & 1;
        const int hf  = sb & 1;
#pragma unroll
        for (int tt = 0; tt < 2; ++tt)
#pragma unroll
            for (int v = 0; v < 7; ++v) {
                const int base = ((bg2 * 14 + tt * 7 + v) * 2 + pr) * 2 + hf;
                const float z = s_partf[base]
                              + s_partf[(4 * 14 * 2) * 2 + base]   // ec=1 block
                              + bias[(t0 + tt) * WW + v];
                gg[tt][v][bb] = pack_dup(1.0f / (1.0f + __expf(-z)));
            }
    }

#pragma unroll
    for (int c = 0; c < 8; ++c) {
        const int e = (c << 7) + (lane << 2);
        const float* xe = x + (size_t)sb0 * SSEQ * EE + e;
        unsigned long long o[2][2][2];
#pragma unroll
        for (int tt = 0; tt < 2; ++tt)
#pragma unroll
            for (int bb = 0; bb < 2; ++bb) {
                o[tt][bb][0] = 0ull; o[tt][bb][1] = 0ull;
            }
#pragma unroll
        for (int i = 0; i < 8; ++i) {
            const int r = t0 - 3 + i;
            if (r >= 0 && r < SSEQ) {
                const ulonglong2 xA = *reinterpret_cast<const ulonglong2*>(
                    xe + (size_t)r * EE);
                const ulonglong2 xB = *reinterpret_cast<const ulonglong2*>(
                    xe + (size_t)(SSEQ + r) * EE);
                if (i < 7) {
                    ffma2(o[0][0][0], gg[0][i][0], xA.x);
                    ffma2(o[0][0][1], gg[0][i][0], xA.y);
                    ffma2(o[0][1][0], gg[0][i][1], xB.x);
                    ffma2(o[0][1][1], gg[0][i][1], xB.y);
                }
                if (i >= 1) {
                    ffma2(o[1][0][0], gg[1][i - 1][0], xA.x);
                    ffma2(o[1][0][1], gg[1][i - 1][0], xA.y);
                    ffma2(o[1][1][0], gg[1][i - 1][1], xB.x);
                    ffma2(o[1][1][1], gg[1][i - 1][1], xB.y);
                }
            }
        }
#pragma unroll
        for (int tt = 0; tt < 2; ++tt)
#pragma unroll
            for (int bb = 0; bb < 2; ++bb) {
                const float2 p0 = unpack2(o[tt][bb][0]);
                const float2 p1 = unpack2(o[tt][bb][1]);
                float4 ov;
                ov.x = tanh_ap(p0.x);
                ov.y = tanh_ap(p0.y);
                ov.z = tanh_ap(p1.x);
                ov.w = tanh_ap(p1.y);
                stg_cs(out + ((size_t)(sb0 + bb) * SSEQ + (tt ? t1 : t0)) * EE + e,
                       ov);
            }
    }
}

extern "C" void kernel_launch(void* const* d_in, const int* in_sizes, int n_in,
                              void* d_out, int out_size) {
    const float* x    = (const float*)d_in[0];
    const float* wgt  = (const float*)d_in[1];
    const float* bias = (const float*)d_in[2];
    float* out        = (float*)d_out;

    static bool attr_set = false;
    if (!attr_set) {
        cudaFuncSetAttribute(soft_reorder_kernel,
                             cudaFuncAttributeMaxDynamicSharedMemorySize,
                             SMEM_BYTES);
        attr_set = true;
    }
    soft_reorder_kernel<<<SSEQ / 2, 256, SMEM_BYTES>>>(x, wgt, bias, out);
}